// round 2
// baseline (speedup 1.0000x reference)
#include <cuda_runtime.h>
#include <math.h>

typedef unsigned long long u64t;

// ---- scratch (device globals; no allocation allowed) ----
static __device__ float g_emb[10240 * 128];
static __device__ float g_S [8 * 18 * 128 * 128];
static __device__ float g_Fm[8 * 9 * 128 * 128];
static __device__ float g_Gm[8 * 9 * 128 * 128];
static __device__ float g_part[64];

// ---- packed fp32x2 helpers ----
__device__ __forceinline__ u64t f2pack(float lo, float hi) {
    u64t r; asm("mov.b64 %0, {%1,%2};" : "=l"(r) : "f"(lo), "f"(hi)); return r;
}
__device__ __forceinline__ void f2unpack(u64t v, float &lo, float &hi) {
    asm("mov.b64 {%0,%1}, %2;" : "=f"(lo), "=f"(hi) : "l"(v));
}
__device__ __forceinline__ u64t ffma2(u64t a, u64t b, u64t c) {
    u64t d; asm("fma.rn.f32x2 %0, %1, %2, %3;" : "=l"(d) : "l"(a), "l"(b), "l"(c)); return d;
}

#define SAS 130  // smem row stride (even -> aligned LDS.64; odd/32 residue limits conflicts)

// Q = scale * (L @ R), all 128x128 in smem with stride SAS. Optional global out (stride 128).
// 256 threads; thread (ti,tj) -> rows ti*8..+7, cols {2*tj+32*p}, p=0..3.
__device__ __forceinline__ void mm128(const float* __restrict__ Ls,
                                      const float* __restrict__ Rs,
                                      float* __restrict__ Qs,
                                      float* __restrict__ gout, float scale)
{
    const int tid = threadIdx.x, ti = tid >> 4, tj = tid & 15, i0 = ti * 8;
    u64t acc[8][4];
#pragma unroll
    for (int a = 0; a < 8; a++)
#pragma unroll
        for (int p = 0; p < 4; p++) acc[a][p] = 0ULL;
#pragma unroll 2
    for (int k = 0; k < 128; k++) {
        u64t ap[8], bp[4];
#pragma unroll
        for (int ii = 0; ii < 8; ii++) { float v = Ls[(i0 + ii) * SAS + k]; ap[ii] = f2pack(v, v); }
#pragma unroll
        for (int p = 0; p < 4; p++) bp[p] = *(const u64t*)(Rs + k * SAS + 2 * tj + 32 * p);
#pragma unroll
        for (int ii = 0; ii < 8; ii++)
#pragma unroll
            for (int p = 0; p < 4; p++) acc[ii][p] = ffma2(ap[ii], bp[p], acc[ii][p]);
    }
#pragma unroll
    for (int ii = 0; ii < 8; ii++)
#pragma unroll
        for (int p = 0; p < 4; p++) {
            float lo, hi; f2unpack(acc[ii][p], lo, hi);
            lo *= scale; hi *= scale;
            const int i = i0 + ii, j = 2 * tj + 32 * p;
            Qs[i * SAS + j] = lo; Qs[i * SAS + j + 1] = hi;
            if (gout) { gout[i * 128 + j] = lo; gout[i * 128 + j + 1] = hi; }
        }
}

// ============================ Kernel 1: fused encoder =======================
__global__ void __launch_bounds__(256, 1)
k_encoder(const float* __restrict__ seq,
          const float* __restrict__ c1w, const float* __restrict__ c1b,
          const float* __restrict__ c2w, const float* __restrict__ c2b,
          const float* __restrict__ lw,  const float* __restrict__ lb)
{
    extern __shared__ float sm[];
    float* s_img  = sm;                 // 2*33*33 = 2178
    float* s_c1w  = s_img + 2178;       // 288
    float* s_c1b  = s_c1w + 288;        // 32
    float* s_h1   = s_c1b + 32;         // 2*32*289 = 18496
    float* s_c2w  = s_h1 + 18496;       // 288*64 = 18432 (transposed: [r][co])
    float* s_c2b  = s_c2w + 18432;      // 64
    float* s_pool = s_c2b + 64;         // 128
    float* s_red  = s_pool + 128;       // 8

    const int tid = threadIdx.x, img0 = blockIdx.x * 2;

    for (int i = tid; i < 2178;  i += 256) s_img[i] = 0.f;
    for (int i = tid; i < 18496; i += 256) s_h1[i]  = 0.f;
    __syncthreads();

    for (int i = tid; i < 2048; i += 256) {
        int im = i >> 10, p = i & 1023;
        s_img[im * 1089 + (p >> 5) * 33 + (p & 31)] = seq[(size_t)(img0 + im) * 1024 + p];
    }
    for (int i = tid; i < 288; i += 256) s_c1w[i] = c1w[i];
    if (tid < 32) s_c1b[tid] = c1b[tid];
    if (tid < 64) s_c2b[tid] = c2b[tid];
    for (int i = tid; i < 18432; i += 256) {
        int co = i / 288, r = i % 288;
        s_c2w[r * 64 + co] = c2w[i];
    }
    __syncthreads();

    // conv1 (1->32, s2, pad lo0/hi1) + relu -> 16x16 in 17x17 (pad row/col 16 = 0)
    {
        const int im = tid >> 7, t7 = tid & 127, cg = t7 >> 3, rp = t7 & 7, c0 = cg * 2;
        float w0[9], w1[9];
#pragma unroll
        for (int q = 0; q < 9; q++) { w0[q] = s_c1w[c0 * 9 + q]; w1[q] = s_c1w[(c0 + 1) * 9 + q]; }
        const float b0 = s_c1b[c0], b1 = s_c1b[c0 + 1];
        const float* ip = s_img + im * 1089;
        float* h0 = s_h1 + (im * 32 + c0) * 289;
        float* h1p = h0 + 289;
#pragma unroll
        for (int yy = 0; yy < 2; yy++) {
            const int y = rp * 2 + yy;
            for (int x = 0; x < 16; x++) {
                float a0 = b0, a1 = b1;
#pragma unroll
                for (int dy = 0; dy < 3; dy++)
#pragma unroll
                    for (int dx = 0; dx < 3; dx++) {
                        float v = ip[(2 * y + dy) * 33 + 2 * x + dx];
                        a0 = fmaf(w0[dy * 3 + dx], v, a0);
                        a1 = fmaf(w1[dy * 3 + dx], v, a1);
                    }
                h0[y * 17 + x]  = fmaxf(a0, 0.f);
                h1p[y * 17 + x] = fmaxf(a1, 0.f);
            }
        }
    }
    __syncthreads();

    // conv2 (32->64, s2) f32x2 + relu + avgpool(8x8)
    {
        const int im = tid >> 7, t7 = tid & 127, g = t7 >> 3, r = t7 & 7;
        u64t acc0[8], acc1[8];
        const u64t bp0 = *(const u64t*)(s_c2b + g * 4);
        const u64t bp1 = *(const u64t*)(s_c2b + g * 4 + 2);
#pragma unroll
        for (int x = 0; x < 8; x++) { acc0[x] = bp0; acc1[x] = bp1; }
        const float* hbase = s_h1 + im * 32 * 289;
#pragma unroll 1
        for (int ci = 0; ci < 32; ci++) {
            const float* hc = hbase + ci * 289;
            const float* wc = s_c2w + ci * 9 * 64;
#pragma unroll
            for (int dy = 0; dy < 3; dy++) {
                const float* hrow = hc + (2 * r + dy) * 17;
#pragma unroll
                for (int dx = 0; dx < 3; dx++) {
                    const u64t w0 = *(const u64t*)(wc + (dy * 3 + dx) * 64 + g * 4);
                    const u64t w1 = *(const u64t*)(wc + (dy * 3 + dx) * 64 + g * 4 + 2);
#pragma unroll
                    for (int x = 0; x < 8; x++) {
                        float v = hrow[2 * x + dx];
                        u64t pv = f2pack(v, v);
                        acc0[x] = ffma2(w0, pv, acc0[x]);
                        acc1[x] = ffma2(w1, pv, acc1[x]);
                    }
                }
            }
        }
        float s[4] = {0.f, 0.f, 0.f, 0.f};
#pragma unroll
        for (int x = 0; x < 8; x++) {
            float e0, e1, e2, e3;
            f2unpack(acc0[x], e0, e1); f2unpack(acc1[x], e2, e3);
            s[0] += fmaxf(e0, 0.f); s[1] += fmaxf(e1, 0.f);
            s[2] += fmaxf(e2, 0.f); s[3] += fmaxf(e3, 0.f);
        }
#pragma unroll
        for (int o = 4; o >= 1; o >>= 1)
#pragma unroll
            for (int c = 0; c < 4; c++) s[c] += __shfl_down_sync(0xffffffffu, s[c], o, 8);
        if (r == 0)
#pragma unroll
            for (int c = 0; c < 4; c++) s_pool[im * 64 + g * 4 + c] = s[c] * (1.f / 64.f);
    }
    __syncthreads();

    // linear (64->128) + L2 normalize
    {
        const int im = tid >> 7, j = tid & 127;
        float e = lb[j];
        const float* pl = s_pool + im * 64;
#pragma unroll 8
        for (int c = 0; c < 64; c++) e = fmaf(pl[c], lw[c * 128 + j], e);
        float ss = e * e;
#pragma unroll
        for (int o = 16; o >= 1; o >>= 1) ss += __shfl_down_sync(0xffffffffu, ss, o);
        if ((tid & 31) == 0) s_red[tid >> 5] = ss;
        __syncthreads();
        float tot = s_red[im * 4] + s_red[im * 4 + 1] + s_red[im * 4 + 2] + s_red[im * 4 + 3];
        g_emb[(size_t)(img0 + im) * 128 + j] = e / fmaxf(sqrtf(tot), 1e-12f);
    }
}

// ====== Kernel 2: A=E_t E_{t+1}^T/tau -> d_out; row-softmax -> S[t]; col-softmax -> S[17-t]
__global__ void __launch_bounds__(256, 1)
k_affinity(float* __restrict__ dout)
{
    extern __shared__ float sm[];
    float* sE1 = sm; float* sE2T = sm + 128 * SAS; float* sA = sm + 2 * 128 * SAS;
    const int bid = blockIdx.x, b = bid / 9, t = bid % 9, tid = threadIdx.x;
    const float* e1 = g_emb + (size_t)(b * 10 + t) * 16384;
    const float* e2 = e1 + 16384;
    for (int i = tid; i < 16384; i += 256) {
        const int n = i >> 7, c = i & 127;
        sE1[n * SAS + c] = e1[i];
        sE2T[c * SAS + n] = e2[i];
    }
    __syncthreads();
    mm128(sE1, sE2T, sA, dout + 1 + (size_t)bid * 16384, 1.0f / 0.07f);
    __syncthreads();
    if (tid < 128) {
        const int n = tid; const float* row = sA + n * SAS;
        float mx = -1e30f;
        for (int m = 0; m < 128; m++) mx = fmaxf(mx, row[m]);
        float sum = 0.f;
        for (int m = 0; m < 128; m++) sum += expf(row[m] - mx);
        const float inv = 1.f / sum;
        float* dst = g_S + ((size_t)(b * 18 + t) * 128 + n) * 128;
        for (int m = 0; m < 128; m++) dst[m] = expf(row[m] - mx) * inv;
    } else {
        const int m = tid - 128;
        float mx = -1e30f;
        for (int n = 0; n < 128; n++) mx = fmaxf(mx, sA[n * SAS + m]);
        float sum = 0.f;
        for (int n = 0; n < 128; n++) sum += expf(sA[n * SAS + m] - mx);
        const float inv = 1.f / sum;
        float* dst = g_S + ((size_t)(b * 18 + (17 - t)) * 128 + m) * 128;
        for (int n = 0; n < 128; n++) dst[n] = expf(sA[n * SAS + m] - mx) * inv;
    }
}

// ====== Kernel 3: prefix chains. dir0: F_s = S[s-1]@F_{s-1}, F_1=I.
//                                 dir1: G_s = G_{s-1}@S[18-s], G_1=S[17].
__global__ void __launch_bounds__(256, 1)
k_chain()
{
    extern __shared__ float sm[];
    float* bufA = sm; float* bufB = sm + 128 * SAS; float* bufM = sm + 2 * 128 * SAS;
    const int b = blockIdx.x >> 1, dir = blockIdx.x & 1, tid = threadIdx.x;
    float* P = bufA; float* Q = bufB;
    float* gdst = (dir ? g_Gm : g_Fm) + (size_t)b * 9 * 16384;
    if (dir == 0) {
        for (int i = tid; i < 16384; i += 256) {
            const float v = ((i >> 7) == (i & 127)) ? 1.f : 0.f;
            P[(i >> 7) * SAS + (i & 127)] = v;
            gdst[16384 + i] = v;
        }
    } else {
        const float* s17 = g_S + (size_t)(b * 18 + 17) * 16384;
        for (int i = tid; i < 16384; i += 256) {
            const float v = s17[i];
            P[(i >> 7) * SAS + (i & 127)] = v;
            gdst[16384 + i] = v;
        }
    }
    for (int s = 2; s <= 8; s++) {
        const int slot = dir ? (18 - s) : (s - 1);
        const float* M = g_S + (size_t)(b * 18 + slot) * 16384;
        __syncthreads();
        for (int i = tid; i < 16384; i += 256)
            bufM[(i >> 7) * SAS + (i & 127)] = M[i];
        __syncthreads();
        const float* L = dir ? P : bufM;
        const float* R = dir ? bufM : P;
        mm128(L, R, Q, gdst + (size_t)s * 16384, 1.0f);
        float* tmp = P; P = Q; Q = tmp;
    }
}

// ====== Kernel 4: At = G_k@F_k; partial = sum_j (colLSE_j - At[j][j])
__global__ void __launch_bounds__(256, 1)
k_loss()
{
    extern __shared__ float sm[];
    float* sG = sm; float* sF = sm + 128 * SAS; float* sA = sm + 2 * 128 * SAS;
    __shared__ float sred[8];
    const int b = blockIdx.x >> 3, kk = (blockIdx.x & 7) + 1, tid = threadIdx.x;
    const float* Gg = g_Gm + (size_t)(b * 9 + kk) * 16384;
    const float* Fg = g_Fm + (size_t)(b * 9 + kk) * 16384;
    for (int i = tid; i < 16384; i += 256) {
        sG[(i >> 7) * SAS + (i & 127)] = Gg[i];
        sF[(i >> 7) * SAS + (i & 127)] = Fg[i];
    }
    __syncthreads();
    mm128(sG, sF, sA, nullptr, 1.0f);
    __syncthreads();
    float part = 0.f;
    if (tid < 128) {
        const int j = tid;
        float mx = -1e30f;
        for (int i = 0; i < 128; i++) mx = fmaxf(mx, sA[i * SAS + j]);
        float sum = 0.f;
        for (int i = 0; i < 128; i++) sum += expf(sA[i * SAS + j] - mx);
        part = (mx + logf(sum)) - sA[j * SAS + j];
    }
#pragma unroll
    for (int o = 16; o >= 1; o >>= 1) part += __shfl_down_sync(0xffffffffu, part, o);
    if ((tid & 31) == 0) sred[tid >> 5] = part;
    __syncthreads();
    if (tid == 0) {
        float s2 = 0.f;
        for (int w = 0; w < 8; w++) s2 += sred[w];
        g_part[blockIdx.x] = s2;
    }
}

__global__ void k_final(float* __restrict__ dout)
{
    if (threadIdx.x == 0) {
        float s = 0.f;
        for (int i = 0; i < 64; i++) s += g_part[i];
        dout[0] = s * (1.f / (8.f * 128.f * 128.f));
    }
}

extern "C" void kernel_launch(void* const* d_in, const int* in_sizes, int n_in,
                              void* d_out, int out_size)
{
    const float* seq = (const float*)d_in[0];
    const float* c1w = (const float*)d_in[1];
    const float* c1b = (const float*)d_in[2];
    const float* c2w = (const float*)d_in[3];
    const float* c2b = (const float*)d_in[4];
    const float* lw  = (const float*)d_in[5];
    const float* lb  = (const float*)d_in[6];
    float* out = (float*)d_out;

    static int configured = 0;
    const int SMEM_ENC = 39626 * 4;
    const int SMEM_MM  = 3 * 128 * SAS * 4;
    if (!configured) {
        cudaFuncSetAttribute(k_encoder,  cudaFuncAttributeMaxDynamicSharedMemorySize, SMEM_ENC);
        cudaFuncSetAttribute(k_affinity, cudaFuncAttributeMaxDynamicSharedMemorySize, SMEM_MM);
        cudaFuncSetAttribute(k_chain,    cudaFuncAttributeMaxDynamicSharedMemorySize, SMEM_MM);
        cudaFuncSetAttribute(k_loss,     cudaFuncAttributeMaxDynamicSharedMemorySize, SMEM_MM);
        configured = 1;
    }

    k_encoder<<<5120, 256, SMEM_ENC>>>(seq, c1w, c1b, c2w, c2b, lw, lb);
    k_affinity<<<72, 256, SMEM_MM>>>(out);
    k_chain<<<16, 256, SMEM_MM>>>();
    k_loss<<<64, 256, SMEM_MM>>>();
    k_final<<<1, 32>>>(out);
}

// round 3
// speedup vs baseline: 2.0824x; 2.0824x over previous
#include <cuda_runtime.h>
#include <math.h>

typedef unsigned long long u64t;

// ---- scratch (device globals; no allocation allowed) ----
static __device__ float g_emb[10240 * 128];
static __device__ float g_S [8 * 18 * 128 * 128];
static __device__ float g_Fm[8 * 9 * 128 * 128];
static __device__ float g_Gm[8 * 9 * 128 * 128];
static __device__ float g_part[64];
static __device__ __align__(16) float g_c2wT[288 * 64];   // conv2 weights, [r][co]

// ---- packed fp32x2 helpers ----
__device__ __forceinline__ u64t f2pack(float lo, float hi) {
    u64t r; asm("mov.b64 %0, {%1,%2};" : "=l"(r) : "f"(lo), "f"(hi)); return r;
}
__device__ __forceinline__ void f2unpack(u64t v, float &lo, float &hi) {
    asm("mov.b64 {%0,%1}, %2;" : "=f"(lo), "=f"(hi) : "l"(v));
}
__device__ __forceinline__ u64t ffma2(u64t a, u64t b, u64t c) {
    u64t d; asm("fma.rn.f32x2 %0, %1, %2, %3;" : "=l"(d) : "l"(a), "l"(b), "l"(c)); return d;
}

#define SAS 130  // smem row stride

// Q = scale * (L @ R). L stride: LG?128(global):SAS(smem). Same for R.
// Qs: smem stride SAS. Optional gout: global row-major 128.
// 256 threads; thread (ti,tj) -> rows ti*8..+7, cols {2*tj+32*p}.
template<bool LG, bool RG>
__device__ __forceinline__ void mm128t(const float* __restrict__ L,
                                       const float* __restrict__ R,
                                       float* __restrict__ Qs,
                                       float* __restrict__ gout, float scale)
{
    const int tid = threadIdx.x, ti = tid >> 4, tj = tid & 15, i0 = ti * 8;
    const int ls = LG ? 128 : SAS, rs = RG ? 128 : SAS;
    u64t acc[8][4];
#pragma unroll
    for (int a = 0; a < 8; a++)
#pragma unroll
        for (int p = 0; p < 4; p++) acc[a][p] = 0ULL;
#pragma unroll 2
    for (int k = 0; k < 128; k++) {
        u64t ap[8], bp[4];
#pragma unroll
        for (int ii = 0; ii < 8; ii++) {
            float v = LG ? __ldg(L + (i0 + ii) * ls + k) : L[(i0 + ii) * ls + k];
            ap[ii] = f2pack(v, v);
        }
#pragma unroll
        for (int p = 0; p < 4; p++) {
            const float* addr = R + k * rs + 2 * tj + 32 * p;
            bp[p] = RG ? __ldg((const u64t*)addr) : *(const u64t*)addr;
        }
#pragma unroll
        for (int ii = 0; ii < 8; ii++)
#pragma unroll
            for (int p = 0; p < 4; p++) acc[ii][p] = ffma2(ap[ii], bp[p], acc[ii][p]);
    }
#pragma unroll
    for (int ii = 0; ii < 8; ii++)
#pragma unroll
        for (int p = 0; p < 4; p++) {
            float lo, hi; f2unpack(acc[ii][p], lo, hi);
            lo *= scale; hi *= scale;
            const int i = i0 + ii, j = 2 * tj + 32 * p;
            Qs[i * SAS + j] = lo; Qs[i * SAS + j + 1] = hi;
            if (gout) { gout[i * 128 + j] = lo; gout[i * 128 + j + 1] = hi; }
        }
}

// ---- Kernel 0: transpose conv2 weights into [r][co] ----
__global__ void k_twt(const float* __restrict__ c2w)
{
    int i = blockIdx.x * 256 + threadIdx.x;
    if (i < 18432) {
        int co = i / 288, r = i % 288;
        g_c2wT[r * 64 + co] = c2w[i];
    }
}

// ============================ Kernel 1: fused encoder =======================
// smem = 21194 floats = 84776 B -> 2 CTAs/SM
__global__ void __launch_bounds__(256, 2)
k_encoder(const float* __restrict__ seq,
          const float* __restrict__ c1w, const float* __restrict__ c1b,
          const float* __restrict__ c2b,
          const float* __restrict__ lw,  const float* __restrict__ lb)
{
    extern __shared__ float sm[];
    float* s_img  = sm;                 // 2*33*33 = 2178
    float* s_c1w  = s_img + 2178;       // 288
    float* s_c1b  = s_c1w + 288;        // 32
    float* s_h1   = s_c1b + 32;         // 2*32*289 = 18496
    float* s_c2b  = s_h1 + 18496;       // 64
    float* s_pool = s_c2b + 64;         // 128
    float* s_red  = s_pool + 128;       // 8

    const int tid = threadIdx.x, img0 = blockIdx.x * 2;

    for (int i = tid; i < 2178;  i += 256) s_img[i] = 0.f;
    for (int i = tid; i < 18496; i += 256) s_h1[i]  = 0.f;
    __syncthreads();

    for (int i = tid; i < 2048; i += 256) {
        int im = i >> 10, p = i & 1023;
        s_img[im * 1089 + (p >> 5) * 33 + (p & 31)] = seq[(size_t)(img0 + im) * 1024 + p];
    }
    for (int i = tid; i < 288; i += 256) s_c1w[i] = c1w[i];
    if (tid < 32) s_c1b[tid] = c1b[tid];
    if (tid < 64) s_c2b[tid] = c2b[tid];
    __syncthreads();

    // conv1 (1->32, s2) + relu -> 16x16 in 17x17 (pad idx 16 = 0)
    {
        const int im = tid >> 7, t7 = tid & 127, cg = t7 >> 3, rp = t7 & 7, c0 = cg * 2;
        float w0[9], w1[9];
#pragma unroll
        for (int q = 0; q < 9; q++) { w0[q] = s_c1w[c0 * 9 + q]; w1[q] = s_c1w[(c0 + 1) * 9 + q]; }
        const float b0 = s_c1b[c0], b1 = s_c1b[c0 + 1];
        const float* ip = s_img + im * 1089;
        float* h0 = s_h1 + (im * 32 + c0) * 289;
        float* h1p = h0 + 289;
#pragma unroll
        for (int yy = 0; yy < 2; yy++) {
            const int y = rp * 2 + yy;
            for (int x = 0; x < 16; x++) {
                float a0 = b0, a1 = b1;
#pragma unroll
                for (int dy = 0; dy < 3; dy++)
#pragma unroll
                    for (int dx = 0; dx < 3; dx++) {
                        float v = ip[(2 * y + dy) * 33 + 2 * x + dx];
                        a0 = fmaf(w0[dy * 3 + dx], v, a0);
                        a1 = fmaf(w1[dy * 3 + dx], v, a1);
                    }
                h0[y * 17 + x]  = fmaxf(a0, 0.f);
                h1p[y * 17 + x] = fmaxf(a1, 0.f);
            }
        }
    }
    __syncthreads();

    // conv2 (32->64, s2): weights via LDG.64 from g_c2wT (L1-resident), f32x2 FMAs
    {
        const int im = tid >> 7, t7 = tid & 127, g = t7 >> 3, r = t7 & 7;
        u64t acc0[8], acc1[8];
        const u64t bp0 = *(const u64t*)(s_c2b + g * 4);
        const u64t bp1 = *(const u64t*)(s_c2b + g * 4 + 2);
#pragma unroll
        for (int x = 0; x < 8; x++) { acc0[x] = bp0; acc1[x] = bp1; }
        const float* hbase = s_h1 + im * 32 * 289;
#pragma unroll 1
        for (int ci = 0; ci < 32; ci++) {
            const float* hc = hbase + ci * 289;
            const float* wc = g_c2wT + ci * 9 * 64;
#pragma unroll
            for (int dy = 0; dy < 3; dy++) {
                const float* hrow = hc + (2 * r + dy) * 17;
#pragma unroll
                for (int dx = 0; dx < 3; dx++) {
                    const u64t w0 = __ldg((const u64t*)(wc + (dy * 3 + dx) * 64 + g * 4));
                    const u64t w1 = __ldg((const u64t*)(wc + (dy * 3 + dx) * 64 + g * 4 + 2));
#pragma unroll
                    for (int x = 0; x < 8; x++) {
                        float v = hrow[2 * x + dx];
                        u64t pv = f2pack(v, v);
                        acc0[x] = ffma2(w0, pv, acc0[x]);
                        acc1[x] = ffma2(w1, pv, acc1[x]);
                    }
                }
            }
        }
        float s[4] = {0.f, 0.f, 0.f, 0.f};
#pragma unroll
        for (int x = 0; x < 8; x++) {
            float e0, e1, e2, e3;
            f2unpack(acc0[x], e0, e1); f2unpack(acc1[x], e2, e3);
            s[0] += fmaxf(e0, 0.f); s[1] += fmaxf(e1, 0.f);
            s[2] += fmaxf(e2, 0.f); s[3] += fmaxf(e3, 0.f);
        }
#pragma unroll
        for (int o = 4; o >= 1; o >>= 1)
#pragma unroll
            for (int c = 0; c < 4; c++) s[c] += __shfl_down_sync(0xffffffffu, s[c], o, 8);
        if (r == 0)
#pragma unroll
            for (int c = 0; c < 4; c++) s_pool[im * 64 + g * 4 + c] = s[c] * (1.f / 64.f);
    }
    __syncthreads();

    // linear (64->128) + L2 normalize
    {
        const int im = tid >> 7, j = tid & 127;
        float e = lb[j];
        const float* pl = s_pool + im * 64;
#pragma unroll 8
        for (int c = 0; c < 64; c++) e = fmaf(pl[c], lw[c * 128 + j], e);
        float ss = e * e;
#pragma unroll
        for (int o = 16; o >= 1; o >>= 1) ss += __shfl_down_sync(0xffffffffu, ss, o);
        if ((tid & 31) == 0) s_red[tid >> 5] = ss;
        __syncthreads();
        float tot = s_red[im * 4] + s_red[im * 4 + 1] + s_red[im * 4 + 2] + s_red[im * 4 + 3];
        g_emb[(size_t)(img0 + im) * 128 + j] = e / fmaxf(sqrtf(tot), 1e-12f);
    }
}

// ====== Kernel 2: A = E_t E_{t+1}^T/tau -> d_out; rowsoftmax -> S[t]; colsoftmax -> S[17-t]
__global__ void __launch_bounds__(256, 1)
k_affinity(float* __restrict__ dout)
{
    extern __shared__ float sm[];
    float* sE2T = sm;                    // 128*SAS
    float* sA   = sm + 16640;            // 128*SAS
    float* srmx = sm + 2 * 16640;        // 128
    float* srin = srmx + 128;            // 128
    float* scmx = srin + 128;            // 128
    float* scin = scmx + 128;            // 128
    const int bid = blockIdx.x, b = bid / 9, t = bid % 9, tid = threadIdx.x;
    const float* e1 = g_emb + (size_t)(b * 10 + t) * 16384;
    const float* e2 = e1 + 16384;

    for (int i = tid; i < 16384; i += 256)
        sE2T[(i & 127) * SAS + (i >> 7)] = e2[i];
    __syncthreads();
    mm128t<true, false>(e1, sE2T, sA, dout + 1 + (size_t)bid * 16384, 1.0f / 0.07f);
    __syncthreads();

    if (tid < 128) {
        const int n = tid; const float* row = sA + n * SAS;
        float mx = -1e30f;
        for (int m = 0; m < 128; m++) mx = fmaxf(mx, row[m]);
        float sum = 0.f;
        for (int m = 0; m < 128; m++) sum += expf(row[m] - mx);
        srmx[n] = mx; srin[n] = 1.f / sum;
    } else {
        const int m = tid - 128;
        float mx = -1e30f;
        for (int n = 0; n < 128; n++) mx = fmaxf(mx, sA[n * SAS + m]);
        float sum = 0.f;
        for (int n = 0; n < 128; n++) sum += expf(sA[n * SAS + m] - mx);
        scmx[m] = mx; scin[m] = 1.f / sum;
    }
    __syncthreads();

    float* dstF = g_S + (size_t)(b * 18 + t) * 16384;
    float* dstB = g_S + (size_t)(b * 18 + (17 - t)) * 16384;
    for (int i = tid; i < 16384; i += 256) {
        const int n = i >> 7, m = i & 127;
        dstF[i] = expf(sA[n * SAS + m] - srmx[n]) * srin[n];
    }
    for (int i = tid; i < 16384; i += 256) {
        const int m = i >> 7, n = i & 127;
        dstB[i] = expf(sA[n * SAS + m] - scmx[m]) * scin[m];
    }
}

// ====== Kernel 3: prefix chains. dir0: F_s = S[s-1]@F_{s-1}, F_1=I.
//                                 dir1: G_s = G_{s-1}@S[18-s], G_1=S[17].
__global__ void __launch_bounds__(256, 1)
k_chain()
{
    extern __shared__ float sm[];
    float* P = sm; float* Q = sm + 16640;
    const int b = blockIdx.x >> 1, dir = blockIdx.x & 1, tid = threadIdx.x;
    float* gdst = (dir ? g_Gm : g_Fm) + (size_t)b * 9 * 16384;
    if (dir == 0) {
        for (int i = tid; i < 16384; i += 256) {
            const float v = ((i >> 7) == (i & 127)) ? 1.f : 0.f;
            P[(i >> 7) * SAS + (i & 127)] = v;
            gdst[16384 + i] = v;
        }
    } else {
        const float* s17 = g_S + (size_t)(b * 18 + 17) * 16384;
        for (int i = tid; i < 16384; i += 256) {
            const float v = s17[i];
            P[(i >> 7) * SAS + (i & 127)] = v;
            gdst[16384 + i] = v;
        }
    }
    __syncthreads();
    for (int s = 2; s <= 8; s++) {
        const int slot = dir ? (18 - s) : (s - 1);
        const float* M = g_S + (size_t)(b * 18 + slot) * 16384;
        if (dir == 0) mm128t<true, false>(M, P, Q, gdst + (size_t)s * 16384, 1.0f);
        else          mm128t<false, true>(P, M, Q, gdst + (size_t)s * 16384, 1.0f);
        __syncthreads();
        float* tmp = P; P = Q; Q = tmp;
    }
}

// ====== Kernel 4: At = G_k@F_k; partial = sum_j (colLSE_j - At[j][j])
__global__ void __launch_bounds__(256, 1)
k_loss()
{
    extern __shared__ float sm[];
    float* sA = sm;
    __shared__ float sred[8];
    const int b = blockIdx.x >> 3, kk = (blockIdx.x & 7) + 1, tid = threadIdx.x;
    const float* Gg = g_Gm + (size_t)(b * 9 + kk) * 16384;
    const float* Fg = g_Fm + (size_t)(b * 9 + kk) * 16384;
    mm128t<true, true>(Gg, Fg, sA, nullptr, 1.0f);
    __syncthreads();
    float part = 0.f;
    if (tid < 128) {
        const int j = tid;
        float mx = -1e30f;
        for (int i = 0; i < 128; i++) mx = fmaxf(mx, sA[i * SAS + j]);
        float sum = 0.f;
        for (int i = 0; i < 128; i++) sum += expf(sA[i * SAS + j] - mx);
        part = (mx + logf(sum)) - sA[j * SAS + j];
    }
#pragma unroll
    for (int o = 16; o >= 1; o >>= 1) part += __shfl_down_sync(0xffffffffu, part, o);
    if ((tid & 31) == 0) sred[tid >> 5] = part;
    __syncthreads();
    if (tid == 0) {
        float s2 = 0.f;
        for (int w = 0; w < 8; w++) s2 += sred[w];
        g_part[blockIdx.x] = s2;
    }
}

__global__ void k_final(float* __restrict__ dout)
{
    if (threadIdx.x == 0) {
        float s = 0.f;
        for (int i = 0; i < 64; i++) s += g_part[i];
        dout[0] = s * (1.f / (8.f * 128.f * 128.f));
    }
}

extern "C" void kernel_launch(void* const* d_in, const int* in_sizes, int n_in,
                              void* d_out, int out_size)
{
    const float* seq = (const float*)d_in[0];
    const float* c1w = (const float*)d_in[1];
    const float* c1b = (const float*)d_in[2];
    const float* c2w = (const float*)d_in[3];
    const float* c2b = (const float*)d_in[4];
    const float* lw  = (const float*)d_in[5];
    const float* lb  = (const float*)d_in[6];
    float* out = (float*)d_out;

    const int SMEM_ENC   = 21194 * 4;                  // 84,776 B
    const int SMEM_AFF   = (2 * 16640 + 512) * 4;      // 135,168 B
    const int SMEM_CHAIN = 2 * 16640 * 4;              // 133,120 B
    const int SMEM_LOSS  = 16640 * 4;                  //  66,560 B

    static int configured = 0;
    if (!configured) {
        cudaFuncSetAttribute(k_encoder,  cudaFuncAttributeMaxDynamicSharedMemorySize, SMEM_ENC);
        cudaFuncSetAttribute(k_affinity, cudaFuncAttributeMaxDynamicSharedMemorySize, SMEM_AFF);
        cudaFuncSetAttribute(k_chain,    cudaFuncAttributeMaxDynamicSharedMemorySize, SMEM_CHAIN);
        cudaFuncSetAttribute(k_loss,     cudaFuncAttributeMaxDynamicSharedMemorySize, SMEM_LOSS);
        configured = 1;
    }

    k_twt<<<72, 256>>>(c2w);
    k_encoder<<<5120, 256, SMEM_ENC>>>(seq, c1w, c1b, c2b, lw, lb);
    k_affinity<<<72, 256, SMEM_AFF>>>(out);
    k_chain<<<16, 256, SMEM_CHAIN>>>();
    k_loss<<<64, 256, SMEM_LOSS>>>();
    k_final<<<1, 32>>>(out);
}

// round 4
// speedup vs baseline: 2.4380x; 1.1708x over previous
#include <cuda_runtime.h>
#include <math.h>

typedef unsigned long long u64t;

// ---- scratch (device globals; no allocation allowed) ----
static __device__ float g_emb[10240 * 128];
static __device__ float g_S [8 * 18 * 128 * 128];
static __device__ float g_Fm[8 * 9 * 128 * 128];
static __device__ float g_Gm[8 * 9 * 128 * 128];
static __device__ float g_At[8 * 8 * 128 * 128];
static __device__ float g_part[64];
static __device__ __align__(16) float g_c2wT[288 * 64];   // conv2 weights, [r][co]

// ---- packed fp32x2 helpers ----
__device__ __forceinline__ u64t f2pack(float lo, float hi) {
    u64t r; asm("mov.b64 %0, {%1,%2};" : "=l"(r) : "f"(lo), "f"(hi)); return r;
}
__device__ __forceinline__ void f2unpack(u64t v, float &lo, float &hi) {
    asm("mov.b64 {%0,%1}, %2;" : "=f"(lo), "=f"(hi) : "l"(v));
}
__device__ __forceinline__ u64t ffma2(u64t a, u64t b, u64t c) {
    u64t d; asm("fma.rn.f32x2 %0, %1, %2, %3;" : "=l"(d) : "l"(a), "l"(b), "l"(c)); return d;
}

// ======== split matmul core: Q[16x128] = scale * (L[16x128] @ R[128x128]) ====
// R staged in smem stride 132 (16B-aligned rows, bank step 4). L rows staged.
// 256 threads: thread (ti=tid>>4 -> row, tj=tid&15 -> cols 2tj+32p).
__device__ __forceinline__ void mm16_core(const float* __restrict__ Lg,
                                          const float* __restrict__ Rg,
                                          float* __restrict__ Qg,
                                          float scale, bool transR, float* sm)
{
    float* sR = sm;           // 128*132 = 16896
    float* sL = sm + 16896;   // 16*132  = 2112
    const int tid = threadIdx.x;
    if (!transR) {
#pragma unroll
        for (int it = 0; it < 16; it++) {
            int i = tid * 4 + it * 1024;
            float4 v = *(const float4*)(Rg + i);
            *(float4*)(sR + (i >> 7) * 132 + (i & 127)) = v;
        }
    } else {
        for (int i = tid; i < 16384; i += 256) {
            int m = i >> 7, c = i & 127;
            sR[c * 132 + m] = Rg[i];
        }
    }
    for (int i = tid; i < 2048; i += 256)
        sL[(i >> 7) * 132 + (i & 127)] = Lg[i];
    __syncthreads();

    const int ti = tid >> 4, tj = tid & 15;
    u64t acc[4] = {0ULL, 0ULL, 0ULL, 0ULL};
#pragma unroll 4
    for (int k = 0; k < 128; k++) {
        float v = sL[ti * 132 + k];
        u64t pv = f2pack(v, v);
#pragma unroll
        for (int p = 0; p < 4; p++) {
            u64t bp = *(const u64t*)(sR + k * 132 + 2 * tj + 32 * p);
            acc[p] = ffma2(pv, bp, acc[p]);
        }
    }
#pragma unroll
    for (int p = 0; p < 4; p++) {
        float lo, hi; f2unpack(acc[p], lo, hi);
        const int j = 2 * tj + 32 * p;
        Qg[ti * 128 + j]     = lo * scale;
        Qg[ti * 128 + j + 1] = hi * scale;
    }
}

// ---- Kernel 0: transpose conv2 weights into [r][co] ----
__global__ void k_twt(const float* __restrict__ c2w)
{
    int i = blockIdx.x * 256 + threadIdx.x;
    if (i < 18432) {
        int co = i / 288, r = i % 288;
        g_c2wT[r * 64 + co] = c2w[i];
    }
}

// ============================ Kernel 1: fused encoder =======================
__global__ void __launch_bounds__(256, 2)
k_encoder(const float* __restrict__ seq,
          const float* __restrict__ c1w, const float* __restrict__ c1b,
          const float* __restrict__ c2b,
          const float* __restrict__ lw,  const float* __restrict__ lb)
{
    extern __shared__ float sm[];
    float* s_img  = sm;                 // 2178
    float* s_c1w  = s_img + 2178;       // 288
    float* s_c1b  = s_c1w + 288;        // 32
    float* s_h1   = s_c1b + 32;         // 18496
    float* s_c2b  = s_h1 + 18496;       // 64
    float* s_pool = s_c2b + 64;         // 128
    float* s_red  = s_pool + 128;       // 8

    const int tid = threadIdx.x, img0 = blockIdx.x * 2;

    for (int i = tid; i < 2178;  i += 256) s_img[i] = 0.f;
    for (int i = tid; i < 18496; i += 256) s_h1[i]  = 0.f;
    __syncthreads();

    for (int i = tid; i < 2048; i += 256) {
        int im = i >> 10, p = i & 1023;
        s_img[im * 1089 + (p >> 5) * 33 + (p & 31)] = seq[(size_t)(img0 + im) * 1024 + p];
    }
    for (int i = tid; i < 288; i += 256) s_c1w[i] = c1w[i];
    if (tid < 32) s_c1b[tid] = c1b[tid];
    if (tid < 64) s_c2b[tid] = c2b[tid];
    __syncthreads();

    // conv1 (1->32, s2) + relu -> 16x16 in 17x17 (pad idx 16 = 0)
    {
        const int im = tid >> 7, t7 = tid & 127, cg = t7 >> 3, rp = t7 & 7, c0 = cg * 2;
        float w0[9], w1[9];
#pragma unroll
        for (int q = 0; q < 9; q++) { w0[q] = s_c1w[c0 * 9 + q]; w1[q] = s_c1w[(c0 + 1) * 9 + q]; }
        const float b0 = s_c1b[c0], b1 = s_c1b[c0 + 1];
        const float* ip = s_img + im * 1089;
        float* h0 = s_h1 + (im * 32 + c0) * 289;
        float* h1p = h0 + 289;
#pragma unroll
        for (int yy = 0; yy < 2; yy++) {
            const int y = rp * 2 + yy;
            for (int x = 0; x < 16; x++) {
                float a0 = b0, a1 = b1;
#pragma unroll
                for (int dy = 0; dy < 3; dy++)
#pragma unroll
                    for (int dx = 0; dx < 3; dx++) {
                        float v = ip[(2 * y + dy) * 33 + 2 * x + dx];
                        a0 = fmaf(w0[dy * 3 + dx], v, a0);
                        a1 = fmaf(w1[dy * 3 + dx], v, a1);
                    }
                h0[y * 17 + x]  = fmaxf(a0, 0.f);
                h1p[y * 17 + x] = fmaxf(a1, 0.f);
            }
        }
    }
    __syncthreads();

    // conv2 (32->64, s2): weights via LDG.64 (L1-resident), f32x2 FMAs
    {
        const int im = tid >> 7, t7 = tid & 127, g = t7 >> 3, r = t7 & 7;
        u64t acc0[8], acc1[8];
        const u64t bp0 = *(const u64t*)(s_c2b + g * 4);
        const u64t bp1 = *(const u64t*)(s_c2b + g * 4 + 2);
#pragma unroll
        for (int x = 0; x < 8; x++) { acc0[x] = bp0; acc1[x] = bp1; }
        const float* hbase = s_h1 + im * 32 * 289;
#pragma unroll 1
        for (int ci = 0; ci < 32; ci++) {
            const float* hc = hbase + ci * 289;
            const float* wc = g_c2wT + ci * 9 * 64;
#pragma unroll
            for (int dy = 0; dy < 3; dy++) {
                const float* hrow = hc + (2 * r + dy) * 17;
#pragma unroll
                for (int dx = 0; dx < 3; dx++) {
                    const u64t w0 = __ldg((const u64t*)(wc + (dy * 3 + dx) * 64 + g * 4));
                    const u64t w1 = __ldg((const u64t*)(wc + (dy * 3 + dx) * 64 + g * 4 + 2));
#pragma unroll
                    for (int x = 0; x < 8; x++) {
                        float v = hrow[2 * x + dx];
                        u64t pv = f2pack(v, v);
                        acc0[x] = ffma2(w0, pv, acc0[x]);
                        acc1[x] = ffma2(w1, pv, acc1[x]);
                    }
                }
            }
        }
        float s[4] = {0.f, 0.f, 0.f, 0.f};
#pragma unroll
        for (int x = 0; x < 8; x++) {
            float e0, e1, e2, e3;
            f2unpack(acc0[x], e0, e1); f2unpack(acc1[x], e2, e3);
            s[0] += fmaxf(e0, 0.f); s[1] += fmaxf(e1, 0.f);
            s[2] += fmaxf(e2, 0.f); s[3] += fmaxf(e3, 0.f);
        }
#pragma unroll
        for (int o = 4; o >= 1; o >>= 1)
#pragma unroll
            for (int c = 0; c < 4; c++) s[c] += __shfl_down_sync(0xffffffffu, s[c], o, 8);
        if (r == 0)
#pragma unroll
            for (int c = 0; c < 4; c++) s_pool[im * 64 + g * 4 + c] = s[c] * (1.f / 64.f);
    }
    __syncthreads();

    // linear (64->128) + L2 normalize
    {
        const int im = tid >> 7, j = tid & 127;
        float e = lb[j];
        const float* pl = s_pool + im * 64;
#pragma unroll 8
        for (int c = 0; c < 64; c++) e = fmaf(pl[c], lw[c * 128 + j], e);
        float ss = e * e;
#pragma unroll
        for (int o = 16; o >= 1; o >>= 1) ss += __shfl_down_sync(0xffffffffu, ss, o);
        if ((tid & 31) == 0) s_red[tid >> 5] = ss;
        __syncthreads();
        float tot = s_red[im * 4] + s_red[im * 4 + 1] + s_red[im * 4 + 2] + s_red[im * 4 + 3];
        g_emb[(size_t)(img0 + im) * 128 + j] = e / fmaxf(sqrtf(tot), 1e-12f);
    }
}

// ====== Kernel 2a: affinity matmul, row-split. Q -> dout (A) ======
__global__ void __launch_bounds__(256, 1)
k_affmm(float* __restrict__ dout)
{
    extern __shared__ float sm[];
    const int rc = blockIdx.x, t = blockIdx.y, b = blockIdx.z;
    const float* E1 = g_emb + (size_t)(b * 10 + t) * 16384;
    const float* E2 = E1 + 16384;
    float* Q = dout + 1 + (size_t)(b * 9 + t) * 16384 + rc * 2048;
    mm16_core(E1 + rc * 2048, E2, Q, 1.0f / 0.07f, true, sm);
}

// ====== Kernel 2b: softmax (rows -> S[t], cols -> S[17-t]) ======
__global__ void __launch_bounds__(256, 1)
k_soft(const float* __restrict__ dout)
{
    extern __shared__ float sm[];
    float* sA = sm;                  // 128*132
    float* srmx = sm + 16896; float* srin = srmx + 128;
    float* scmx = srin + 128; float* scin = scmx + 128;
    const int bid = blockIdx.x, b = bid / 9, t = bid % 9, tid = threadIdx.x;
    const float* A = dout + 1 + (size_t)bid * 16384;
    for (int i = tid; i < 16384; i += 256)
        sA[(i >> 7) * 132 + (i & 127)] = A[i];
    __syncthreads();
    if (tid < 128) {
        const int n = tid; const float* row = sA + n * 132;
        float mx = -1e30f;
        for (int m = 0; m < 128; m++) mx = fmaxf(mx, row[m]);
        float s = 0.f;
        for (int m = 0; m < 128; m++) s += expf(row[m] - mx);
        srmx[n] = mx; srin[n] = 1.f / s;
    } else {
        const int m = tid - 128;
        float mx = -1e30f;
        for (int n = 0; n < 128; n++) mx = fmaxf(mx, sA[n * 132 + m]);
        float s = 0.f;
        for (int n = 0; n < 128; n++) s += expf(sA[n * 132 + m] - mx);
        scmx[m] = mx; scin[m] = 1.f / s;
    }
    __syncthreads();
    float* dstF = g_S + (size_t)(b * 18 + t) * 16384;
    float* dstB = g_S + (size_t)(b * 18 + 17 - t) * 16384;
    for (int i = tid; i < 16384; i += 256) {
        const int n = i >> 7, m = i & 127;
        dstF[i] = expf(sA[n * 132 + m] - srmx[n]) * srin[n];
    }
    for (int i = tid; i < 16384; i += 256) {
        const int m = i >> 7, n = i & 127;
        dstB[i] = expf(sA[n * 132 + m] - scmx[m]) * scin[m];
    }
}

// ====== Kernel 3a: chain init (slot 1): F1 = I, G1 = S[17] ======
__global__ void k_init()
{
    const int rc = blockIdx.x, dir = blockIdx.y, b = blockIdx.z, tid = threadIdx.x;
    float* dst = (dir ? g_Gm : g_Fm) + ((size_t)b * 9 + 1) * 16384 + rc * 2048;
    if (dir == 0) {
        for (int i = tid; i < 2048; i += 256)
            dst[i] = ((rc * 16 + (i >> 7)) == (i & 127)) ? 1.f : 0.f;
    } else {
        const float* src = g_S + (size_t)(b * 18 + 17) * 16384 + rc * 2048;
        for (int i = tid; i < 2048; i += 256) dst[i] = src[i];
    }
}

// ====== Kernel 3b: chain step s (launched 7x, s=2..8) ======
__global__ void __launch_bounds__(256, 1)
k_step(int s)
{
    extern __shared__ float sm[];
    const int rc = blockIdx.x, dir = blockIdx.y, b = blockIdx.z;
    const float *L, *R; float* Q;
    if (dir == 0) {   // F_s = S[s-1] @ F_{s-1}
        L = g_S  + (size_t)(b * 18 + s - 1) * 16384 + rc * 2048;
        R = g_Fm + ((size_t)b * 9 + s - 1) * 16384;
        Q = g_Fm + ((size_t)b * 9 + s) * 16384 + rc * 2048;
    } else {          // G_s = G_{s-1} @ S[18-s]
        L = g_Gm + ((size_t)b * 9 + s - 1) * 16384 + rc * 2048;
        R = g_S  + (size_t)(b * 18 + 18 - s) * 16384;
        Q = g_Gm + ((size_t)b * 9 + s) * 16384 + rc * 2048;
    }
    mm16_core(L, R, Q, 1.0f, false, sm);
}

// ====== Kernel 4a: At_k = G_k @ F_k -> g_At ======
__global__ void __launch_bounds__(256, 1)
k_lossmm()
{
    extern __shared__ float sm[];
    const int rc = blockIdx.x, kidx = blockIdx.y, b = blockIdx.z;
    const float* L = g_Gm + ((size_t)b * 9 + kidx + 1) * 16384 + rc * 2048;
    const float* R = g_Fm + ((size_t)b * 9 + kidx + 1) * 16384;
    float* Q = g_At + (size_t)(b * 8 + kidx) * 16384 + rc * 2048;
    mm16_core(L, R, Q, 1.0f, false, sm);
}

// ====== Kernel 4b: partial loss = sum_j (colLSE_j - At[j][j]) ======
__global__ void __launch_bounds__(256, 1)
k_loss2()
{
    extern __shared__ float sm[];
    float* sA = sm;   // 128*132
    __shared__ float sred[8];
    const int bid = blockIdx.x, tid = threadIdx.x;
    const float* At = g_At + (size_t)bid * 16384;
#pragma unroll
    for (int it = 0; it < 16; it++) {
        int i = tid * 4 + it * 1024;
        float4 v = *(const float4*)(At + i);
        *(float4*)(sA + (i >> 7) * 132 + (i & 127)) = v;
    }
    __syncthreads();
    float part = 0.f;
    if (tid < 128) {
        const int j = tid;
        float mx = -1e30f;
        for (int i = 0; i < 128; i++) mx = fmaxf(mx, sA[i * 132 + j]);
        float s = 0.f;
        for (int i = 0; i < 128; i++) s += expf(sA[i * 132 + j] - mx);
        part = (mx + logf(s)) - sA[j * 132 + j];
    }
#pragma unroll
    for (int o = 16; o >= 1; o >>= 1) part += __shfl_down_sync(0xffffffffu, part, o);
    if ((tid & 31) == 0) sred[tid >> 5] = part;
    __syncthreads();
    if (tid == 0) {
        float s2 = 0.f;
        for (int w = 0; w < 8; w++) s2 += sred[w];
        g_part[bid] = s2;
    }
}

__global__ void k_final(float* __restrict__ dout)
{
    if (threadIdx.x == 0) {
        float s = 0.f;
        for (int i = 0; i < 64; i++) s += g_part[i];
        dout[0] = s * (1.f / (8.f * 128.f * 128.f));
    }
}

extern "C" void kernel_launch(void* const* d_in, const int* in_sizes, int n_in,
                              void* d_out, int out_size)
{
    const float* seq = (const float*)d_in[0];
    const float* c1w = (const float*)d_in[1];
    const float* c1b = (const float*)d_in[2];
    const float* c2w = (const float*)d_in[3];
    const float* c2b = (const float*)d_in[4];
    const float* lw  = (const float*)d_in[5];
    const float* lb  = (const float*)d_in[6];
    float* out = (float*)d_out;

    const int SMEM_ENC  = 21194 * 4;          // 84,776 B
    const int SMEM_MM   = 19008 * 4;          // 76,032 B (sR + sL)
    const int SMEM_SOFT = 17408 * 4;          // 69,632 B
    const int SMEM_L2   = 16896 * 4;          // 67,584 B

    static int configured = 0;
    if (!configured) {
        cudaFuncSetAttribute(k_encoder, cudaFuncAttributeMaxDynamicSharedMemorySize, SMEM_ENC);
        cudaFuncSetAttribute(k_affmm,   cudaFuncAttributeMaxDynamicSharedMemorySize, SMEM_MM);
        cudaFuncSetAttribute(k_step,    cudaFuncAttributeMaxDynamicSharedMemorySize, SMEM_MM);
        cudaFuncSetAttribute(k_lossmm,  cudaFuncAttributeMaxDynamicSharedMemorySize, SMEM_MM);
        cudaFuncSetAttribute(k_soft,    cudaFuncAttributeMaxDynamicSharedMemorySize, SMEM_SOFT);
        cudaFuncSetAttribute(k_loss2,   cudaFuncAttributeMaxDynamicSharedMemorySize, SMEM_L2);
        configured = 1;
    }

    k_twt<<<72, 256>>>(c2w);
    k_encoder<<<5120, 256, SMEM_ENC>>>(seq, c1w, c1b, c2b, lw, lb);
    k_affmm<<<dim3(8, 9, 8), 256, SMEM_MM>>>(out);
    k_soft<<<72, 256, SMEM_SOFT>>>(out);
    k_init<<<dim3(8, 2, 8), 256>>>();
    for (int s = 2; s <= 8; s++)
        k_step<<<dim3(8, 2, 8), 256, SMEM_MM>>>(s);
    k_lossmm<<<dim3(8, 8, 8), 256, SMEM_MM>>>();
    k_loss2<<<64, 256, SMEM_L2>>>();
    k_final<<<1, 32>>>(out);
}